// round 7
// baseline (speedup 1.0000x reference)
#include <cuda_runtime.h>
#include <cuda_bf16.h>
#include <math.h>

// Problem constants
#define BB 4
#define SS 1024
#define EE 1024
#define HH 16
#define DKK 64
#define PER (BB * HH * SS * DKK)   // 4194304 elems per q/k/v tensor
#define NEGV (-10000.0f)

// ---------------------------------------------------------------------------
// Scratch: bf16 hi/lo pairs, packed as u32 words (2 bf16 along k) for GEMMs
// ---------------------------------------------------------------------------
__device__ unsigned g_xh[4096 * 512],  g_xl[4096 * 512];    // x
__device__ unsigned g_qwh[3072 * 512], g_qwl[3072 * 512];   // qkv_w
__device__ unsigned g_owh[1024 * 512], g_owl[1024 * 512];   // out_w
__device__ unsigned g_cth[4096 * 512], g_ctl[4096 * 512];   // ctx [B*S, E]
__device__ __nv_bfloat16 g_qh[3 * PER], g_ql[3 * PER];      // q|k|v hi/lo

// ---------------------------------------------------------------------------
// helpers
// ---------------------------------------------------------------------------
__device__ __forceinline__ void mma_bf16(float* d, const unsigned* a,
                                         unsigned b0, unsigned b1)
{
    asm("mma.sync.aligned.m16n8k16.row.col.f32.bf16.bf16.f32 "
        "{%0,%1,%2,%3}, {%4,%5,%6,%7}, {%8,%9}, {%0,%1,%2,%3};"
        : "+f"(d[0]), "+f"(d[1]), "+f"(d[2]), "+f"(d[3])
        : "r"(a[0]), "r"(a[1]), "r"(a[2]), "r"(a[3]), "r"(b0), "r"(b1));
}

__device__ __forceinline__ unsigned pack_hi(float x, float y,
                                            float& rx, float& ry)
{
    __nv_bfloat162 t = __floats2bfloat162_rn(x, y);
    rx = x - __bfloat162float(t.x);
    ry = y - __bfloat162float(t.y);
    unsigned u; *(__nv_bfloat162*)&u = t; return u;
}
__device__ __forceinline__ unsigned pack_lo(float rx, float ry)
{
    __nv_bfloat162 t = __floats2bfloat162_rn(rx, ry);
    unsigned u; *(__nv_bfloat162*)&u = t; return u;
}

__device__ __forceinline__ void cpa16(unsigned dst, const void* src)
{
    asm volatile("cp.async.cg.shared.global [%0], [%1], 16;"
                 :: "r"(dst), "l"(src));
}
__device__ __forceinline__ void cpa_commit()
{
    asm volatile("cp.async.commit_group;");
}
__device__ __forceinline__ void cpa_wait0()
{
    asm volatile("cp.async.wait_group 0;");
}

// ---------------------------------------------------------------------------
// Prep: fp32 -> bf16 hi/lo word arrays. which: 0=x, 1=qkv_w, 2=out_w
// ---------------------------------------------------------------------------
__global__ void cvt_kernel(const float* __restrict__ src, int which, int n4)
{
    unsigned* dh = (which == 0) ? g_xh : (which == 1) ? g_qwh : g_owh;
    unsigned* dl = (which == 0) ? g_xl : (which == 1) ? g_qwl : g_owl;
    const int i = blockIdx.x * blockDim.x + threadIdx.x;
    if (i < n4) {
        float4 v = ((const float4*)src)[i];
        float rx, ry;
        unsigned h0 = pack_hi(v.x, v.y, rx, ry);
        unsigned l0 = pack_lo(rx, ry);
        unsigned h1 = pack_hi(v.z, v.w, rx, ry);
        unsigned l1 = pack_lo(rx, ry);
        dh[2 * i] = h0; dh[2 * i + 1] = h1;
        dl[2 * i] = l0; dl[2 * i + 1] = l1;
    }
}

// ---------------------------------------------------------------------------
// GEMM (unchanged from Round 6 — known good)
// ---------------------------------------------------------------------------
#define KW 20

template <int MODE>
__global__ __launch_bounds__(256, 2) void gemm_bf16_kernel(
    const float* __restrict__ bias, const unsigned int* __restrict__ kpm,
    float* __restrict__ out)
{
    extern __shared__ unsigned dynsm[];
    const unsigned *Ah, *Al, *Wh, *Wl;
    if (MODE == 0) { Ah = g_xh;  Al = g_xl;  Wh = g_qwh; Wl = g_qwl; }
    else           { Ah = g_cth; Al = g_ctl; Wh = g_owh; Wl = g_owl; }

    const int tid = threadIdx.x, lane = tid & 31, warp = tid >> 5;
    const int wm = warp >> 1, wn = warp & 1;
    const int m0 = blockIdx.y * 128, n0 = blockIdx.x * 128;
    const int r = lane >> 2, cc = lane & 3;

    const unsigned sbase = (unsigned)__cvta_generic_to_shared(dynsm);

    const int c0 = tid, c1 = tid + 256;
    const int row0 = c0 >> 2, off0 = (c0 & 3) * 4;
    const int row1 = c1 >> 2, off1 = (c1 & 3) * 4;
    const unsigned so0 = (unsigned)(row0 * KW + off0) * 4u;
    const unsigned so1 = (unsigned)(row1 * KW + off1) * 4u;
    const size_t ga0 = (size_t)(m0 + row0) * 512 + off0;
    const size_t ga1 = (size_t)(m0 + row1) * 512 + off1;
    const size_t gb0 = (size_t)(n0 + row0) * 512 + off0;
    const size_t gb1 = (size_t)(n0 + row1) * 512 + off1;

    float acc[2][8][4];
#pragma unroll
    for (int i = 0; i < 2; i++)
#pragma unroll
        for (int j = 0; j < 8; j++)
#pragma unroll
            for (int c = 0; c < 4; c++) acc[i][j][c] = 0.0f;

#define ISSUE(kt, st) do {                                                  \
    const int kk_ = (kt) * 16;                                              \
    const unsigned sb_ = sbase + (unsigned)(st) * 40960u;                   \
    cpa16(sb_ +      0u + so0, Ah + ga0 + kk_);                             \
    cpa16(sb_ +      0u + so1, Ah + ga1 + kk_);                             \
    cpa16(sb_ + 10240u + so0, Al + ga0 + kk_);                              \
    cpa16(sb_ + 10240u + so1, Al + ga1 + kk_);                              \
    cpa16(sb_ + 20480u + so0, Wh + gb0 + kk_);                              \
    cpa16(sb_ + 20480u + so1, Wh + gb1 + kk_);                              \
    cpa16(sb_ + 30720u + so0, Wl + gb0 + kk_);                              \
    cpa16(sb_ + 30720u + so1, Wl + gb1 + kk_);                              \
    cpa_commit(); } while (0)

    ISSUE(0, 0);

    for (int kt = 0; kt < 32; kt++) {
        cpa_wait0();
        __syncthreads();
        if (kt < 31) ISSUE(kt + 1, (kt + 1) & 1);

        const unsigned* pAh = dynsm + (kt & 1) * 10240 + 0 * 2560;
        const unsigned* pAl = dynsm + (kt & 1) * 10240 + 1 * 2560;
        const unsigned* pBh = dynsm + (kt & 1) * 10240 + 2 * 2560;
        const unsigned* pBl = dynsm + (kt & 1) * 10240 + 3 * 2560;

#pragma unroll
        for (int half = 0; half < 2; half++) {
            const int kwb = half * 8;
            unsigned ah[2][4], al[2][4];
#pragma unroll
            for (int mi = 0; mi < 2; mi++) {
                const int mrow = wm * 32 + mi * 16 + r;
                ah[mi][0] = pAh[mrow * KW + kwb + cc];
                ah[mi][1] = pAh[(mrow + 8) * KW + kwb + cc];
                ah[mi][2] = pAh[mrow * KW + kwb + 4 + cc];
                ah[mi][3] = pAh[(mrow + 8) * KW + kwb + 4 + cc];
                al[mi][0] = pAl[mrow * KW + kwb + cc];
                al[mi][1] = pAl[(mrow + 8) * KW + kwb + cc];
                al[mi][2] = pAl[mrow * KW + kwb + 4 + cc];
                al[mi][3] = pAl[(mrow + 8) * KW + kwb + 4 + cc];
            }
#pragma unroll
            for (int ni = 0; ni < 8; ni++) {
                const int ncol = wn * 64 + ni * 8 + r;
                const unsigned bh0 = pBh[ncol * KW + kwb + cc];
                const unsigned bh1 = pBh[ncol * KW + kwb + 4 + cc];
                const unsigned bl0 = pBl[ncol * KW + kwb + cc];
                const unsigned bl1 = pBl[ncol * KW + kwb + 4 + cc];
#pragma unroll
                for (int mi = 0; mi < 2; mi++) {
                    mma_bf16(acc[mi][ni], ah[mi], bh0, bh1);
                    mma_bf16(acc[mi][ni], ah[mi], bl0, bl1);
                    mma_bf16(acc[mi][ni], al[mi], bh0, bh1);
                }
            }
        }
        __syncthreads();
    }
#undef ISSUE

#pragma unroll
    for (int mi = 0; mi < 2; mi++) {
        const int mbase = m0 + wm * 32 + mi * 16 + r;
#pragma unroll
        for (int rr = 0; rr < 2; rr++) {
            const int m = mbase + rr * 8;
            if (MODE == 0) {
                const int b = m >> 10, s = m & 1023;
                const bool pad = (kpm[b * 1024 + s] != 0u);
#pragma unroll
                for (int ni = 0; ni < 8; ni++) {
                    const int c = n0 + wn * 64 + ni * 8 + cc * 2;
                    const float v0 = pad ? 0.0f : (acc[mi][ni][rr * 2]     + bias[c]);
                    const float v1 = pad ? 0.0f : (acc[mi][ni][rr * 2 + 1] + bias[c + 1]);
                    const int which = c >> 10;
                    const int e = c & 1023;
                    const int hh = e >> 6, d = e & 63;
                    const size_t idx = (size_t)which * PER
                                     + ((size_t)(b * HH + hh) * SS + s) * DKK + d;
                    __nv_bfloat162 hv, lv;
                    hv.x = __float2bfloat16(v0);
                    lv.x = __float2bfloat16(v0 - __bfloat162float(hv.x));
                    hv.y = __float2bfloat16(v1);
                    lv.y = __float2bfloat16(v1 - __bfloat162float(hv.y));
                    *(__nv_bfloat162*)&g_qh[idx] = hv;
                    *(__nv_bfloat162*)&g_ql[idx] = lv;
                }
            } else {
#pragma unroll
                for (int ni = 0; ni < 8; ni++) {
                    const int n = n0 + wn * 64 + ni * 8 + cc * 2;
                    out[(size_t)m * 1024 + n]     = acc[mi][ni][rr * 2]     + bias[n];
                    out[(size_t)m * 1024 + n + 1] = acc[mi][ni][rr * 2 + 1] + bias[n + 1];
                }
            }
        }
    }
}

// ---------------------------------------------------------------------------
// Single-pass attention. CTA = (b, h, 32 q rows), 512 threads (16 warps).
// Full score row (32 x 1024 fp32) lives in smem. Phases:
//   1) S = QK^T/8 + causal + pad   (split-MMA, causal tiles skipped)
//   2) exact softmax per row in smem; single normalized-weights gmem write
//   3) ctx = W @ V (split-MMA, W packed hi/lo on the fly from smem fp32)
// ---------------------------------------------------------------------------
#define QB 32
#define SP 1038  // score row stride (fp32 words); odd*2 to spread banks
#define QS 36
#define WS 68

__global__ __launch_bounds__(512) void attn_fused_kernel(
    const unsigned int* __restrict__ kpm, float* __restrict__ wout)
{
    extern __shared__ unsigned sm[];
    float*    scores = (float*)sm;          // 32 * 1038 = 33216 words
    unsigned* sQh = sm + 33216;             // 32*36 = 1152
    unsigned* sQl = sQh + 1152;
    unsigned* sKh = sQl + 1152;             // 128*36 = 4608
    unsigned* sKl = sKh + 4608;
    unsigned* sVh = sKl + 4608;             // 64*68 = 4352
    unsigned* sVl = sVh + 4352;
    unsigned* sKp = sVl + 4352;             // 128

    const int b = blockIdx.z, h = blockIdx.y, q0 = blockIdx.x * QB;
    const int tid = threadIdx.x, lane = tid & 31, w = tid >> 5;
    const int r = lane >> 2, cc = lane & 3;

    const unsigned* qhw = (const unsigned*)g_qh;
    const unsigned* qlw = (const unsigned*)g_ql;
    const size_t qbase = ((size_t)(b * HH + h) * SS + q0) * 32;
    const size_t kbase = (size_t)PER / 2 + ((size_t)(b * HH + h) * SS) * 32;
    const size_t vbase = (size_t)PER     + ((size_t)(b * HH + h) * SS) * 32;

    // ---- Q tile load (32 rows x 32 words hi/lo)
    if (tid < 256) {
        const int row = tid >> 3, off = (tid & 7) * 4;
        *(uint4*)&sQh[row * QS + off] = *(const uint4*)(qhw + qbase + row * 32 + off);
        *(uint4*)&sQl[row * QS + off] = *(const uint4*)(qlw + qbase + row * 32 + off);
    }
    __syncthreads();

    // ---- Phase 1: scores
    const int wmS = w >> 3;       // 0..1 (16-row group)
    const int wnS = w & 7;        // 0..7 (16-key group per 128-tile)
    const int qr = wmS * 16 + r;
    const int row0g = q0 + qr, row1g = row0g + 8;

    unsigned aQh[4][4], aQl[4][4];
#pragma unroll
    for (int ks = 0; ks < 4; ks++) {
        const int bw = ks * 8 + cc;
        aQh[ks][0] = sQh[qr * QS + bw];
        aQh[ks][1] = sQh[(qr + 8) * QS + bw];
        aQh[ks][2] = sQh[qr * QS + bw + 4];
        aQh[ks][3] = sQh[(qr + 8) * QS + bw + 4];
        aQl[ks][0] = sQl[qr * QS + bw];
        aQl[ks][1] = sQl[(qr + 8) * QS + bw];
        aQl[ks][2] = sQl[qr * QS + bw + 4];
        aQl[ks][3] = sQl[(qr + 8) * QS + bw + 4];
    }

    const int ntmax = blockIdx.x >> 2;   // last key tile touching row q0+31

    for (int nt = 0; nt <= ntmax; nt++) {
        __syncthreads();
        for (int i = tid; i < 1024; i += 512) {
            const int row = i >> 3, off = (i & 7) * 4;
            const size_t g = kbase + (size_t)(nt * 128 + row) * 32 + off;
            *(uint4*)&sKh[row * QS + off] = *(const uint4*)(qhw + g);
            *(uint4*)&sKl[row * QS + off] = *(const uint4*)(qlw + g);
        }
        if (tid < 128) sKp[tid] = kpm[b * 1024 + nt * 128 + tid];
        __syncthreads();

        float acc[2][4];
#pragma unroll
        for (int ni = 0; ni < 2; ni++)
#pragma unroll
            for (int c = 0; c < 4; c++) acc[ni][c] = 0.0f;

#pragma unroll
        for (int ks = 0; ks < 4; ks++) {
            const int bw = ks * 8 + cc;
#pragma unroll
            for (int ni = 0; ni < 2; ni++) {
                const int krow = wnS * 16 + ni * 8 + r;
                const unsigned bh0 = sKh[krow * QS + bw];
                const unsigned bh1 = sKh[krow * QS + bw + 4];
                const unsigned bl0 = sKl[krow * QS + bw];
                const unsigned bl1 = sKl[krow * QS + bw + 4];
                mma_bf16(acc[ni], aQh[ks], bh0, bh1);
                mma_bf16(acc[ni], aQh[ks], bl0, bl1);
                mma_bf16(acc[ni], aQl[ks], bh0, bh1);
            }
        }

#pragma unroll
        for (int ni = 0; ni < 2; ni++) {
            const int colb = wnS * 16 + ni * 8 + cc * 2;
            const int col = nt * 128 + colb;
#pragma unroll
            for (int e = 0; e < 2; e++) {
                const bool pad = (sKp[colb + e] != 0u);
                float s0 = acc[ni][e] * 0.125f;
                if (col + e > row0g) s0 += NEGV;
                if (pad) s0 = NEGV;
                acc[ni][e] = s0;
                float s1 = acc[ni][2 + e] * 0.125f;
                if (col + e > row1g) s1 += NEGV;
                if (pad) s1 = NEGV;
                acc[ni][2 + e] = s1;
            }
            *(float2*)&scores[qr * SP + col]       = make_float2(acc[ni][0], acc[ni][1]);
            *(float2*)&scores[(qr + 8) * SP + col] = make_float2(acc[ni][2], acc[ni][3]);
        }
    }
    __syncthreads();

    // ---- Phase 2: exact softmax + single weights write (warp owns 2 rows)
    const int valid = (ntmax + 1) * 128;
#pragma unroll
    for (int t = 0; t < 2; t++) {
        const int rr = w * 2 + t;
        float* srow = scores + rr * SP;
        float m = -1e30f;
        for (int j = lane; j < valid; j += 32) m = fmaxf(m, srow[j]);
#pragma unroll
        for (int off = 16; off; off >>= 1)
            m = fmaxf(m, __shfl_xor_sync(0xFFFFFFFFu, m, off));
        float l = 0.0f;
        for (int j = lane; j < valid; j += 32) {
            const float e = __expf(srow[j] - m);
            srow[j] = e;
            l += e;
        }
#pragma unroll
        for (int off = 16; off; off >>= 1)
            l += __shfl_xor_sync(0xFFFFFFFFu, l, off);
        const float li = 1.0f / l;
        float* grow = wout + ((size_t)(b * HH + h) * SS + q0 + rr) * SS;
        for (int j = lane * 2; j < valid; j += 64) {
            float2 e2 = *(float2*)&srow[j];
            e2.x *= li; e2.y *= li;
            *(float2*)&srow[j] = e2;
            *(float2*)&grow[j] = e2;
        }
        const float4 z4 = make_float4(0.f, 0.f, 0.f, 0.f);
        for (int j = valid + lane * 4; j < 1024; j += 128)
            *(float4*)&grow[j] = z4;
    }
    __syncthreads();

    // ---- Phase 3: ctx = W @ V
    const int wmP = w >> 3, wnP = w & 7;   // rows 16-group, dims 8-block
    const int qr2 = wmP * 16 + r;
    float accO[4] = {0.f, 0.f, 0.f, 0.f};

    for (int kt = 0; kt <= ntmax; kt++) {
        __syncthreads();
        {
            __nv_bfloat16* tVh = (__nv_bfloat16*)sVh;
            __nv_bfloat16* tVl = (__nv_bfloat16*)sVl;
            for (int i = tid; i < 4096; i += 512) {
                const int key = i >> 5, dw = i & 31;
                const size_t g = vbase + (size_t)(kt * 128 + key) * 32 + dw;
                unsigned whd = qhw[g];
                unsigned wld = qlw[g];
                __nv_bfloat162 h2 = *(__nv_bfloat162*)&whd;
                __nv_bfloat162 l2 = *(__nv_bfloat162*)&wld;
                tVh[(2 * dw) * (2 * WS) + key]     = h2.x;
                tVh[(2 * dw + 1) * (2 * WS) + key] = h2.y;
                tVl[(2 * dw) * (2 * WS) + key]     = l2.x;
                tVl[(2 * dw + 1) * (2 * WS) + key] = l2.y;
            }
        }
        __syncthreads();

#pragma unroll
        for (int ks = 0; ks < 8; ks++) {
            const int kb = kt * 128 + ks * 16;
            float2 f0 = *(float2*)&scores[qr2 * SP + kb + 2 * cc];
            float2 f1 = *(float2*)&scores[(qr2 + 8) * SP + kb + 2 * cc];
            float2 f2 = *(float2*)&scores[qr2 * SP + kb + 8 + 2 * cc];
            float2 f3 = *(float2*)&scores[(qr2 + 8) * SP + kb + 8 + 2 * cc];
            unsigned ah[4], al[4];
            float rx, ry;
            ah[0] = pack_hi(f0.x, f0.y, rx, ry); al[0] = pack_lo(rx, ry);
            ah[1] = pack_hi(f1.x, f1.y, rx, ry); al[1] = pack_lo(rx, ry);
            ah[2] = pack_hi(f2.x, f2.y, rx, ry); al[2] = pack_lo(rx, ry);
            ah[3] = pack_hi(f3.x, f3.y, rx, ry); al[3] = pack_lo(rx, ry);

            const int bw = ks * 8 + cc;
            const int vrow = wnP * 8 + r;
            const unsigned bh0 = sVh[vrow * WS + bw];
            const unsigned bh1 = sVh[vrow * WS + bw + 4];
            const unsigned bl0 = sVl[vrow * WS + bw];
            const unsigned bl1 = sVl[vrow * WS + bw + 4];
            mma_bf16(accO, ah, bh0, bh1);
            mma_bf16(accO, ah, bl0, bl1);
            mma_bf16(accO, al, bh0, bh1);
        }
    }

    // ctx epilogue (bf16 hi/lo for out-projection)
    {
        __nv_bfloat16* cth = (__nv_bfloat16*)g_cth;
        __nv_bfloat16* ctl = (__nv_bfloat16*)g_ctl;
        const int d0 = wnP * 8 + cc * 2;
        const size_t o0 = ((size_t)(b * SS + q0 + qr2)) * EE + h * DKK + d0;
        const size_t o1 = ((size_t)(b * SS + q0 + qr2 + 8)) * EE + h * DKK + d0;
        __nv_bfloat162 hv, lv;
        hv.x = __float2bfloat16(accO[0]);
        lv.x = __float2bfloat16(accO[0] - __bfloat162float(hv.x));
        hv.y = __float2bfloat16(accO[1]);
        lv.y = __float2bfloat16(accO[1] - __bfloat162float(hv.y));
        *(__nv_bfloat162*)(cth + o0) = hv;
        *(__nv_bfloat162*)(ctl + o0) = lv;
        hv.x = __float2bfloat16(accO[2]);
        lv.x = __float2bfloat16(accO[2] - __bfloat162float(hv.x));
        hv.y = __float2bfloat16(accO[3]);
        lv.y = __float2bfloat16(accO[3] - __bfloat162float(hv.y));
        *(__nv_bfloat162*)(cth + o1) = hv;
        *(__nv_bfloat162*)(ctl + o1) = lv;
    }
}

// ---------------------------------------------------------------------------
extern "C" void kernel_launch(void* const* d_in, const int* in_sizes, int n_in,
                              void* d_out, int out_size)
{
    const float*        x     = (const float*)d_in[0];
    const unsigned int* kpm   = (const unsigned int*)d_in[2];
    const float*        qkv_w = (const float*)d_in[3];
    const float*        qkv_b = (const float*)d_in[4];
    const float*        out_w = (const float*)d_in[5];
    const float*        out_b = (const float*)d_in[6];

    float* out  = (float*)d_out;
    float* wout = out + (size_t)BB * SS * EE;

    const int gemmSmem = 2 * 4 * 2560 * 4;   // 80 KB
    const int attnSmem = (33216 + 2 * 1152 + 2 * 4608 + 2 * 4352 + 128) * 4; // 214272
    cudaFuncSetAttribute(gemm_bf16_kernel<0>,
                         cudaFuncAttributeMaxDynamicSharedMemorySize, gemmSmem);
    cudaFuncSetAttribute(gemm_bf16_kernel<1>,
                         cudaFuncAttributeMaxDynamicSharedMemorySize, gemmSmem);
    cudaFuncSetAttribute(attn_fused_kernel,
                         cudaFuncAttributeMaxDynamicSharedMemorySize, attnSmem);

    // 0) one-time conversions
    cvt_kernel<<<4096, 256>>>(x,     0, 4096 * 256);
    cvt_kernel<<<3072, 256>>>(qkv_w, 1, 3072 * 256);
    cvt_kernel<<<1024, 256>>>(out_w, 2, 1024 * 256);

    // 1) QKV projection -> g_qh/g_ql
    gemm_bf16_kernel<0><<<dim3(24, 32), 256, gemmSmem>>>(qkv_b, kpm, nullptr);

    // 2) fused attention: weights -> d_out tail, ctx -> g_cth/g_ctl
    attn_fused_kernel<<<dim3(32, HH, BB), 512, attnSmem>>>(kpm, wout);

    // 3) output projection
    gemm_bf16_kernel<1><<<dim3(8, 32), 256, gemmSmem>>>(out_b, nullptr, out);
}

// round 8
// speedup vs baseline: 1.1466x; 1.1466x over previous
#include <cuda_runtime.h>
#include <cuda_bf16.h>
#include <math.h>

// Problem constants
#define BB 4
#define SS 1024
#define EE 1024
#define HH 16
#define DKK 64
#define PER (BB * HH * SS * DKK)
#define NEGV (-10000.0f)

// ---------------------------------------------------------------------------
// Scratch: bf16 hi/lo pairs, packed as u32 words (2 bf16 along k)
// ---------------------------------------------------------------------------
__device__ unsigned g_xh[4096 * 512],  g_xl[4096 * 512];    // x
__device__ unsigned g_qwh[3072 * 512], g_qwl[3072 * 512];   // qkv_w
__device__ unsigned g_owh[1024 * 512], g_owl[1024 * 512];   // out_w
__device__ unsigned g_cth[4096 * 512], g_ctl[4096 * 512];   // ctx [B*S, E]
__device__ __nv_bfloat16 g_qh[3 * PER], g_ql[3 * PER];      // q|k|v hi/lo
__device__ float g_m[BB * HH * SS];                         // row max
__device__ float g_linv[BB * HH * SS];                      // 1/row denom

// ---------------------------------------------------------------------------
// helpers
// ---------------------------------------------------------------------------
__device__ __forceinline__ void mma_bf16(float* d, const unsigned* a,
                                         unsigned b0, unsigned b1)
{
    asm("mma.sync.aligned.m16n8k16.row.col.f32.bf16.bf16.f32 "
        "{%0,%1,%2,%3}, {%4,%5,%6,%7}, {%8,%9}, {%0,%1,%2,%3};"
        : "+f"(d[0]), "+f"(d[1]), "+f"(d[2]), "+f"(d[3])
        : "r"(a[0]), "r"(a[1]), "r"(a[2]), "r"(a[3]), "r"(b0), "r"(b1));
}

// ldmatrix x4: addr(lane) = base + ((rowbase + (lane&15))*stride + (lane>>4)*4)*4B
__device__ __forceinline__ void ldsm4(unsigned* rg, unsigned addr)
{
    asm volatile("ldmatrix.sync.aligned.m8n8.x4.shared.b16 {%0,%1,%2,%3}, [%4];"
                 : "=r"(rg[0]), "=r"(rg[1]), "=r"(rg[2]), "=r"(rg[3])
                 : "r"(addr));
}

__device__ __forceinline__ unsigned pack_hi(float x, float y,
                                            float& rx, float& ry)
{
    __nv_bfloat162 t = __floats2bfloat162_rn(x, y);
    rx = x - __bfloat162float(t.x);
    ry = y - __bfloat162float(t.y);
    unsigned u; *(__nv_bfloat162*)&u = t; return u;
}
__device__ __forceinline__ unsigned pack_lo(float rx, float ry)
{
    __nv_bfloat162 t = __floats2bfloat162_rn(rx, ry);
    unsigned u; *(__nv_bfloat162*)&u = t; return u;
}

__device__ __forceinline__ void cpa16(unsigned dst, const void* src)
{
    asm volatile("cp.async.cg.shared.global [%0], [%1], 16;"
                 :: "r"(dst), "l"(src));
}
__device__ __forceinline__ void cpa_commit()
{
    asm volatile("cp.async.commit_group;");
}
__device__ __forceinline__ void cpa_wait0()
{
    asm volatile("cp.async.wait_group 0;");
}

// ---------------------------------------------------------------------------
// Prep: fp32 -> bf16 hi/lo word arrays. which: 0=x, 1=qkv_w, 2=out_w
// ---------------------------------------------------------------------------
__global__ void cvt_kernel(const float* __restrict__ src, int which, int n4)
{
    unsigned* dh = (which == 0) ? g_xh : (which == 1) ? g_qwh : g_owh;
    unsigned* dl = (which == 0) ? g_xl : (which == 1) ? g_qwl : g_owl;
    const int i = blockIdx.x * blockDim.x + threadIdx.x;
    if (i < n4) {
        float4 v = ((const float4*)src)[i];
        float rx, ry;
        unsigned h0 = pack_hi(v.x, v.y, rx, ry);
        unsigned l0 = pack_lo(rx, ry);
        unsigned h1 = pack_hi(v.z, v.w, rx, ry);
        unsigned l1 = pack_lo(rx, ry);
        dh[2 * i] = h0; dh[2 * i + 1] = h1;
        dl[2 * i] = l0; dl[2 * i + 1] = l1;
    }
}

// ---------------------------------------------------------------------------
// GEMM: 128x128 tile, cp.async double-buffered, ldmatrix fragment loads.
// MODE 0: A=x, W=qkv_w -> scatter g_qh/g_ql (pad zeroed)
// MODE 1: A=ctx, W=out_w -> fp32 out
// ---------------------------------------------------------------------------
#define KW 20

template <int MODE>
__global__ __launch_bounds__(256, 2) void gemm_bf16_kernel(
    const float* __restrict__ bias, const unsigned int* __restrict__ kpm,
    float* __restrict__ out)
{
    extern __shared__ unsigned dynsm[];   // [2 stages][Ah Al Wh Wl][2560]
    const unsigned *Ah, *Al, *Wh, *Wl;
    if (MODE == 0) { Ah = g_xh;  Al = g_xl;  Wh = g_qwh; Wl = g_qwl; }
    else           { Ah = g_cth; Al = g_ctl; Wh = g_owh; Wl = g_owl; }

    const int tid = threadIdx.x, lane = tid & 31, warp = tid >> 5;
    const int wm = warp >> 1, wn = warp & 1;
    const int m0 = blockIdx.y * 128, n0 = blockIdx.x * 128;
    const int r = lane >> 2, cc = lane & 3;
    const int lrow16 = lane & 15;
    const int lkoff4 = (lane >> 4) * 4;

    const unsigned sbase = (unsigned)__cvta_generic_to_shared(dynsm);

    const int c0 = tid, c1 = tid + 256;
    const int row0 = c0 >> 2, off0 = (c0 & 3) * 4;
    const int row1 = c1 >> 2, off1 = (c1 & 3) * 4;
    const unsigned so0 = (unsigned)(row0 * KW + off0) * 4u;
    const unsigned so1 = (unsigned)(row1 * KW + off1) * 4u;
    const size_t ga0 = (size_t)(m0 + row0) * 512 + off0;
    const size_t ga1 = (size_t)(m0 + row1) * 512 + off1;
    const size_t gb0 = (size_t)(n0 + row0) * 512 + off0;
    const size_t gb1 = (size_t)(n0 + row1) * 512 + off1;

    float acc[2][8][4];
#pragma unroll
    for (int i = 0; i < 2; i++)
#pragma unroll
        for (int j = 0; j < 8; j++)
#pragma unroll
            for (int c = 0; c < 4; c++) acc[i][j][c] = 0.0f;

#define ISSUE(kt, st) do {                                                  \
    const int kk_ = (kt) * 16;                                              \
    const unsigned sb_ = sbase + (unsigned)(st) * 40960u;                   \
    cpa16(sb_ +      0u + so0, Ah + ga0 + kk_);                             \
    cpa16(sb_ +      0u + so1, Ah + ga1 + kk_);                             \
    cpa16(sb_ + 10240u + so0, Al + ga0 + kk_);                              \
    cpa16(sb_ + 10240u + so1, Al + ga1 + kk_);                              \
    cpa16(sb_ + 20480u + so0, Wh + gb0 + kk_);                              \
    cpa16(sb_ + 20480u + so1, Wh + gb1 + kk_);                              \
    cpa16(sb_ + 30720u + so0, Wl + gb0 + kk_);                              \
    cpa16(sb_ + 30720u + so1, Wl + gb1 + kk_);                              \
    cpa_commit(); } while (0)

    ISSUE(0, 0);

    for (int kt = 0; kt < 32; kt++) {
        cpa_wait0();
        __syncthreads();
        if (kt < 31) ISSUE(kt + 1, (kt + 1) & 1);

        const unsigned stoff = sbase + (unsigned)(kt & 1) * 40960u;

#pragma unroll
        for (int half = 0; half < 2; half++) {
            const int kwb = half * 8;
            unsigned ah[2][4], al[2][4];
#pragma unroll
            for (int mi = 0; mi < 2; mi++) {
                const unsigned aoff = (unsigned)
                    ((wm * 32 + mi * 16 + lrow16) * KW + kwb + lkoff4) * 4u;
                ldsm4(ah[mi], stoff + aoff);
                ldsm4(al[mi], stoff + 10240u + aoff);
            }
#pragma unroll
            for (int p = 0; p < 4; p++) {
                const unsigned boff = (unsigned)
                    ((wn * 64 + p * 16 + lrow16) * KW + kwb + lkoff4) * 4u;
                unsigned bh[4], bl[4];
                ldsm4(bh, stoff + 20480u + boff);
                ldsm4(bl, stoff + 30720u + boff);
#pragma unroll
                for (int mi = 0; mi < 2; mi++) {
                    mma_bf16(acc[mi][2 * p],     ah[mi], bh[0], bh[2]);
                    mma_bf16(acc[mi][2 * p],     ah[mi], bl[0], bl[2]);
                    mma_bf16(acc[mi][2 * p],     al[mi], bh[0], bh[2]);
                    mma_bf16(acc[mi][2 * p + 1], ah[mi], bh[1], bh[3]);
                    mma_bf16(acc[mi][2 * p + 1], ah[mi], bl[1], bl[3]);
                    mma_bf16(acc[mi][2 * p + 1], al[mi], bh[1], bh[3]);
                }
            }
        }
        __syncthreads();
    }
#undef ISSUE

#pragma unroll
    for (int mi = 0; mi < 2; mi++) {
        const int mbase = m0 + wm * 32 + mi * 16 + r;
#pragma unroll
        for (int rr = 0; rr < 2; rr++) {
            const int m = mbase + rr * 8;
            if (MODE == 0) {
                const int b = m >> 10, s = m & 1023;
                const bool pad = (kpm[b * 1024 + s] != 0u);
#pragma unroll
                for (int ni = 0; ni < 8; ni++) {
                    const int c = n0 + wn * 64 + ni * 8 + cc * 2;
                    const float v0 = pad ? 0.0f : (acc[mi][ni][rr * 2]     + bias[c]);
                    const float v1 = pad ? 0.0f : (acc[mi][ni][rr * 2 + 1] + bias[c + 1]);
                    const int which = c >> 10;
                    const int e = c & 1023;
                    const int hh = e >> 6, d = e & 63;
                    const size_t idx = (size_t)which * PER
                                     + ((size_t)(b * HH + hh) * SS + s) * DKK + d;
                    __nv_bfloat162 hv, lv;
                    hv.x = __float2bfloat16(v0);
                    lv.x = __float2bfloat16(v0 - __bfloat162float(hv.x));
                    hv.y = __float2bfloat16(v1);
                    lv.y = __float2bfloat16(v1 - __bfloat162float(hv.y));
                    *(__nv_bfloat162*)&g_qh[idx] = hv;
                    *(__nv_bfloat162*)&g_ql[idx] = lv;
                }
            } else {
#pragma unroll
                for (int ni = 0; ni < 8; ni++) {
                    const int n = n0 + wn * 64 + ni * 8 + cc * 2;
                    out[(size_t)m * 1024 + n]     = acc[mi][ni][rr * 2]     + bias[n];
                    out[(size_t)m * 1024 + n + 1] = acc[mi][ni][rr * 2 + 1] + bias[n + 1];
                }
            }
        }
    }
}

// ---------------------------------------------------------------------------
// Attention Pass A: raw scores -> wout (valid tiles only), stats -> g_m/g_linv
// CTA = (b, h, 128 q rows); tiles nt > blockIdx.x skipped (fully masked).
// ---------------------------------------------------------------------------
#define QS 36

__global__ __launch_bounds__(256) void attn_score_kernel(
    const unsigned int* __restrict__ kpm, float* __restrict__ wout)
{
    extern __shared__ unsigned sm[];
    unsigned* sQh = sm;                     // 128*36
    unsigned* sQl = sQh + 128 * QS;
    unsigned* sKh = sQl + 128 * QS;
    unsigned* sKl = sKh + 128 * QS;
    unsigned* sKp = sKl + 128 * QS;

    const int b = blockIdx.z, h = blockIdx.y, q0 = blockIdx.x * 128;
    const int tid = threadIdx.x, lane = tid & 31, w = tid >> 5;
    const int r = lane >> 2, cc = lane & 3;
    const int lrow16 = lane & 15;
    const int lkoff4 = (lane >> 4) * 4;

    const unsigned sKh_u = (unsigned)__cvta_generic_to_shared(sKh);
    const unsigned KLOFF = 128u * QS * 4u;  // sKl - sKh in bytes

    const unsigned* qhw = (const unsigned*)g_qh;
    const unsigned* qlw = (const unsigned*)g_ql;
    const size_t qbase = ((size_t)(b * HH + h) * SS + q0) * 32;
    const size_t kbase = (size_t)PER / 2 + ((size_t)(b * HH + h) * SS) * 32;

    for (int i = tid; i < 1024; i += 256) {
        const int row = i >> 3, off = (i & 7) * 4;
        *(uint4*)&sQh[row * QS + off] = *(const uint4*)(qhw + qbase + row * 32 + off);
        *(uint4*)&sQl[row * QS + off] = *(const uint4*)(qlw + qbase + row * 32 + off);
    }
    __syncthreads();

    const int qr = w * 16 + r;
    unsigned aQh[4][4], aQl[4][4];
#pragma unroll
    for (int ks = 0; ks < 4; ks++) {
        const int bw = ks * 8 + cc;
        aQh[ks][0] = sQh[qr * QS + bw];
        aQh[ks][1] = sQh[(qr + 8) * QS + bw];
        aQh[ks][2] = sQh[qr * QS + bw + 4];
        aQh[ks][3] = sQh[(qr + 8) * QS + bw + 4];
        aQl[ks][0] = sQl[qr * QS + bw];
        aQl[ks][1] = sQl[(qr + 8) * QS + bw];
        aQl[ks][2] = sQl[qr * QS + bw + 4];
        aQl[ks][3] = sQl[(qr + 8) * QS + bw + 4];
    }

    const int row0 = q0 + qr, row1 = row0 + 8;
    float* wrow0 = wout + ((size_t)(b * HH + h) * SS + row0) * SS;
    float* wrow1 = wout + ((size_t)(b * HH + h) * SS + row1) * SS;

    float m_run[2] = {-1e30f, -1e30f};
    float l_run[2] = {0.0f, 0.0f};

    const int ntmax = blockIdx.x;
    for (int nt = 0; nt <= ntmax; nt++) {
        __syncthreads();
        for (int i = tid; i < 1024; i += 256) {
            const int row = i >> 3, off = (i & 7) * 4;
            const size_t g = kbase + (size_t)(nt * 128 + row) * 32 + off;
            *(uint4*)&sKh[row * QS + off] = *(const uint4*)(qhw + g);
            *(uint4*)&sKl[row * QS + off] = *(const uint4*)(qlw + g);
        }
        if (tid < 128) sKp[tid] = kpm[b * 1024 + nt * 128 + tid];
        __syncthreads();

        float acc[16][4];
#pragma unroll
        for (int ni = 0; ni < 16; ni++)
#pragma unroll
            for (int c = 0; c < 4; c++) acc[ni][c] = 0.0f;

#pragma unroll
        for (int ks = 0; ks < 4; ks++) {
#pragma unroll
            for (int p = 0; p < 8; p++) {
                const unsigned koff = (unsigned)
                    ((p * 16 + lrow16) * QS + ks * 8 + lkoff4) * 4u;
                unsigned bh[4], bl[4];
                ldsm4(bh, sKh_u + koff);
                ldsm4(bl, sKh_u + KLOFF + koff);
                mma_bf16(acc[2 * p],     aQh[ks], bh[0], bh[2]);
                mma_bf16(acc[2 * p],     aQh[ks], bl[0], bl[2]);
                mma_bf16(acc[2 * p],     aQl[ks], bh[0], bh[2]);
                mma_bf16(acc[2 * p + 1], aQh[ks], bh[1], bh[3]);
                mma_bf16(acc[2 * p + 1], aQh[ks], bl[1], bl[3]);
                mma_bf16(acc[2 * p + 1], aQl[ks], bh[1], bh[3]);
            }
        }

#pragma unroll
        for (int ni = 0; ni < 16; ni++) {
            const int colb = ni * 8 + cc * 2;
            const int col = nt * 128 + colb;
#pragma unroll
            for (int e = 0; e < 2; e++) {
                const bool pad = (sKp[colb + e] != 0u);
                float s0 = acc[ni][e] * 0.125f;
                if (col + e > row0) s0 += NEGV;
                if (pad) s0 = NEGV;
                acc[ni][e] = s0;
                float s1 = acc[ni][2 + e] * 0.125f;
                if (col + e > row1) s1 += NEGV;
                if (pad) s1 = NEGV;
                acc[ni][2 + e] = s1;
            }
            *(float2*)(wrow0 + col) = make_float2(acc[ni][0], acc[ni][1]);
            *(float2*)(wrow1 + col) = make_float2(acc[ni][2], acc[ni][3]);
        }

        float tm0 = -1e30f, tm1 = -1e30f;
#pragma unroll
        for (int ni = 0; ni < 16; ni++) {
            tm0 = fmaxf(tm0, fmaxf(acc[ni][0], acc[ni][1]));
            tm1 = fmaxf(tm1, fmaxf(acc[ni][2], acc[ni][3]));
        }
        tm0 = fmaxf(tm0, __shfl_xor_sync(0xFFFFFFFFu, tm0, 1));
        tm0 = fmaxf(tm0, __shfl_xor_sync(0xFFFFFFFFu, tm0, 2));
        tm1 = fmaxf(tm1, __shfl_xor_sync(0xFFFFFFFFu, tm1, 1));
        tm1 = fmaxf(tm1, __shfl_xor_sync(0xFFFFFFFFu, tm1, 2));
        const float nm0 = fmaxf(m_run[0], tm0);
        const float nm1 = fmaxf(m_run[1], tm1);
        float s0 = 0.0f, s1 = 0.0f;
#pragma unroll
        for (int ni = 0; ni < 16; ni++) {
            s0 += __expf(acc[ni][0] - nm0) + __expf(acc[ni][1] - nm0);
            s1 += __expf(acc[ni][2] - nm1) + __expf(acc[ni][3] - nm1);
        }
        s0 += __shfl_xor_sync(0xFFFFFFFFu, s0, 1);
        s0 += __shfl_xor_sync(0xFFFFFFFFu, s0, 2);
        s1 += __shfl_xor_sync(0xFFFFFFFFu, s1, 1);
        s1 += __shfl_xor_sync(0xFFFFFFFFu, s1, 2);
        l_run[0] = l_run[0] * __expf(m_run[0] - nm0) + s0;
        l_run[1] = l_run[1] * __expf(m_run[1] - nm1) + s1;
        m_run[0] = nm0; m_run[1] = nm1;
    }

    if (cc == 0) {
        const int sb_ = (b * HH + h) * SS;
        g_m[sb_ + row0] = m_run[0];
        g_m[sb_ + row1] = m_run[1];
        g_linv[sb_ + row0] = 1.0f / l_run[0];
        g_linv[sb_ + row1] = 1.0f / l_run[1];
    }
}

// ---------------------------------------------------------------------------
// Attention Pass B: w = exp(s-m)/l (write back), ctx = W @ V (hi/lo bf16 out).
// Fully-masked tiles: zero weights, skip compute.
// ---------------------------------------------------------------------------
#define WS 68

__global__ __launch_bounds__(256) void attn_av_kernel(float* __restrict__ wout)
{
    extern __shared__ unsigned sm[];
    unsigned* sWh = sm;                     // 128*68
    unsigned* sWl = sWh + 128 * WS;
    unsigned* sVh = sWl + 128 * WS;         // 64*68
    unsigned* sVl = sVh + 64 * WS;
    float*    sM  = (float*)(sVl + 64 * WS);
    float*    sLi = sM + 128;

    const int b = blockIdx.z, h = blockIdx.y, q0 = blockIdx.x * 128;
    const int tid = threadIdx.x, lane = tid & 31, w = tid >> 5;
    const int r = lane >> 2, cc = lane & 3;
    const int lrow16 = lane & 15;
    const int lkoff4 = (lane >> 4) * 4;

    const unsigned sWh_u = (unsigned)__cvta_generic_to_shared(sWh);
    const unsigned sVh_u = (unsigned)__cvta_generic_to_shared(sVh);
    const unsigned WLOFF = 128u * WS * 4u;
    const unsigned VLOFF = 64u * WS * 4u;

    const unsigned* vhw = (const unsigned*)g_qh + (size_t)PER
                        + ((size_t)(b * HH + h) * SS) * 32;
    const unsigned* vlw = (const unsigned*)g_ql + (size_t)PER
                        + ((size_t)(b * HH + h) * SS) * 32;
    float* wbase = wout + ((size_t)(b * HH + h) * SS + q0) * SS;

    if (tid < 128) {
        const int sb_ = (b * HH + h) * SS + q0;
        sM[tid]  = g_m[sb_ + tid];
        sLi[tid] = g_linv[sb_ + tid];
    }
    __syncthreads();

    float acc[8][4];
#pragma unroll
    for (int ni = 0; ni < 8; ni++)
#pragma unroll
        for (int c = 0; c < 4; c++) acc[ni][c] = 0.0f;

    const int ktmax = blockIdx.x;

    for (int kt = 0; kt <= ktmax; kt++) {
        if (kt > 0) __syncthreads();
        for (int i = tid; i < 4096; i += 256) {
            const int row = i >> 5, c4 = (i & 31) * 4;
            float* p = wbase + (size_t)row * SS + kt * 128 + c4;
            float4 s = *(const float4*)p;
            const float mm = sM[row], li = sLi[row];
            float4 wv;
            wv.x = __expf(s.x - mm) * li;
            wv.y = __expf(s.y - mm) * li;
            wv.z = __expf(s.z - mm) * li;
            wv.w = __expf(s.w - mm) * li;
            *(float4*)p = wv;
            float rx, ry;
            unsigned h0 = pack_hi(wv.x, wv.y, rx, ry); unsigned l0 = pack_lo(rx, ry);
            unsigned h1 = pack_hi(wv.z, wv.w, rx, ry); unsigned l1 = pack_lo(rx, ry);
            const int base = row * WS + (c4 >> 1);
            sWh[base] = h0; sWh[base + 1] = h1;
            sWl[base] = l0; sWl[base + 1] = l1;
        }
        {
            __nv_bfloat16* tVh = (__nv_bfloat16*)sVh;
            __nv_bfloat16* tVl = (__nv_bfloat16*)sVl;
            for (int i = tid; i < 4096; i += 256) {
                const int key = i >> 5, dw = i & 31;
                const size_t g = (size_t)(kt * 128 + key) * 32 + dw;
                unsigned wh = vhw[g];
                unsigned wl = vlw[g];
                __nv_bfloat162 h2 = *(__nv_bfloat162*)&wh;
                __nv_bfloat162 l2 = *(__nv_bfloat162*)&wl;
                tVh[(2 * dw) * (2 * WS) + key]     = h2.x;
                tVh[(2 * dw + 1) * (2 * WS) + key] = h2.y;
                tVl[(2 * dw) * (2 * WS) + key]     = l2.x;
                tVl[(2 * dw + 1) * (2 * WS) + key] = l2.y;
            }
        }
        __syncthreads();

#pragma unroll
        for (int ks = 0; ks < 8; ks++) {
            const unsigned woff = (unsigned)
                ((w * 16 + lrow16) * WS + ks * 8 + lkoff4) * 4u;
            unsigned ah[4], al[4];
            ldsm4(ah, sWh_u + woff);
            ldsm4(al, sWh_u + WLOFF + woff);
#pragma unroll
            for (int p = 0; p < 4; p++) {
                const unsigned voff = (unsigned)
                    ((p * 16 + lrow16) * WS + ks * 8 + lkoff4) * 4u;
                unsigned bh[4], bl[4];
                ldsm4(bh, sVh_u + voff);
                ldsm4(bl, sVh_u + VLOFF + voff);
                mma_bf16(acc[2 * p],     ah, bh[0], bh[2]);
                mma_bf16(acc[2 * p],     ah, bl[0], bl[2]);
                mma_bf16(acc[2 * p],     al, bh[0], bh[2]);
                mma_bf16(acc[2 * p + 1], ah, bh[1], bh[3]);
                mma_bf16(acc[2 * p + 1], ah, bl[1], bl[3]);
                mma_bf16(acc[2 * p + 1], al, bh[1], bh[3]);
            }
        }
    }

    // zero-fill weights for fully-masked tiles
    {
        const float4 z4 = make_float4(0.f, 0.f, 0.f, 0.f);
        for (int kt = ktmax + 1; kt < 8; kt++)
            for (int i = tid; i < 4096; i += 256) {
                const int row = i >> 5, c4 = (i & 31) * 4;
                *(float4*)(wbase + (size_t)row * SS + kt * 128 + c4) = z4;
            }
    }

    // ctx epilogue: hi/lo bf16
    __nv_bfloat16* cth = (__nv_bfloat16*)g_cth;
    __nv_bfloat16* ctl = (__nv_bfloat16*)g_ctl;
    const int qr = w * 16 + r;
    const size_t o0 = ((size_t)(b * SS + q0 + qr)) * EE + h * DKK;
    const size_t o1 = ((size_t)(b * SS + q0 + qr + 8)) * EE + h * DKK;
#pragma unroll
    for (int ni = 0; ni < 8; ni++) {
        const int d0 = ni * 8 + cc * 2;
        __nv_bfloat162 hv, lv;
        hv.x = __float2bfloat16(acc[ni][0]);
        lv.x = __float2bfloat16(acc[ni][0] - __bfloat162float(hv.x));
        hv.y = __float2bfloat16(acc[ni][1]);
        lv.y = __float2bfloat16(acc[ni][1] - __bfloat162float(hv.y));
        *(__nv_bfloat162*)(cth + o0 + d0) = hv;
        *(__nv_bfloat162*)(ctl + o0 + d0) = lv;
        hv.x = __float2bfloat16(acc[ni][2]);
        lv.x = __float2bfloat16(acc[ni][2] - __bfloat162float(hv.x));
        hv.y = __float2bfloat16(acc[ni][3]);
        lv.y = __float2bfloat16(acc[ni][3] - __bfloat162float(hv.y));
        *(__nv_bfloat162*)(cth + o1 + d0) = hv;
        *(__nv_bfloat162*)(ctl + o1 + d0) = lv;
    }
}

// ---------------------------------------------------------------------------
extern "C" void kernel_launch(void* const* d_in, const int* in_sizes, int n_in,
                              void* d_out, int out_size)
{
    const float*        x     = (const float*)d_in[0];
    const unsigned int* kpm   = (const unsigned int*)d_in[2];
    const float*        qkv_w = (const float*)d_in[3];
    const float*        qkv_b = (const float*)d_in[4];
    const float*        out_w = (const float*)d_in[5];
    const float*        out_b = (const float*)d_in[6];

    float* out  = (float*)d_out;
    float* wout = out + (size_t)BB * SS * EE;

    const int gemmSmem  = 2 * 4 * 2560 * 4;                         // 80 KB
    const int scoreSmem = (4 * 128 * QS + 128) * 4;                 // ~74 KB
    const int avSmem    = (2 * 128 * WS + 2 * 64 * WS + 256) * 4;   // ~105 KB
    cudaFuncSetAttribute(gemm_bf16_kernel<0>,
                         cudaFuncAttributeMaxDynamicSharedMemorySize, gemmSmem);
    cudaFuncSetAttribute(gemm_bf16_kernel<1>,
                         cudaFuncAttributeMaxDynamicSharedMemorySize, gemmSmem);
    cudaFuncSetAttribute(attn_score_kernel,
                         cudaFuncAttributeMaxDynamicSharedMemorySize, scoreSmem);
    cudaFuncSetAttribute(attn_av_kernel,
                         cudaFuncAttributeMaxDynamicSharedMemorySize, avSmem);

    // 0) one-time conversions
    cvt_kernel<<<4096, 256>>>(x,     0, 4096 * 256);
    cvt_kernel<<<3072, 256>>>(qkv_w, 1, 3072 * 256);
    cvt_kernel<<<1024, 256>>>(out_w, 2, 1024 * 256);

    // 1) QKV projection -> g_qh/g_ql
    gemm_bf16_kernel<0><<<dim3(24, 32), 256, gemmSmem>>>(qkv_b, kpm, nullptr);

    // 2a) scores + stats
    attn_score_kernel<<<dim3(8, HH, BB), 256, scoreSmem>>>(kpm, wout);

    // 2b) softmax weights + ctx
    attn_av_kernel<<<dim3(8, HH, BB), 256, avSmem>>>(wout);

    // 3) output projection
    gemm_bf16_kernel<1><<<dim3(8, 32), 256, gemmSmem>>>(out_b, nullptr, out);
}

// round 9
// speedup vs baseline: 1.1475x; 1.0008x over previous
#include <cuda_runtime.h>
#include <cuda_bf16.h>
#include <math.h>

// Problem constants
#define BB 4
#define SS 1024
#define EE 1024
#define HH 16
#define DKK 64
#define PER (BB * HH * SS * DKK)
#define NEGV (-10000.0f)

// ---------------------------------------------------------------------------
// Scratch: bf16 hi/lo pairs, packed as u32 words (2 bf16 along k)
// ---------------------------------------------------------------------------
__device__ unsigned g_xh[4096 * 512],  g_xl[4096 * 512];    // x
__device__ unsigned g_qwh[3072 * 512], g_qwl[3072 * 512];   // qkv_w
__device__ unsigned g_owh[1024 * 512], g_owl[1024 * 512];   // out_w
__device__ unsigned g_cth[4096 * 512], g_ctl[4096 * 512];   // ctx [B*S, E]
__device__ __nv_bfloat16 g_qh[3 * PER], g_ql[3 * PER];      // q|k|v hi/lo
__device__ float g_m[BB * HH * SS];                         // row max
__device__ float g_linv[BB * HH * SS];                      // 1/row denom

// ---------------------------------------------------------------------------
// helpers
// ---------------------------------------------------------------------------
__device__ __forceinline__ void mma_bf16(float* d, const unsigned* a,
                                         unsigned b0, unsigned b1)
{
    asm("mma.sync.aligned.m16n8k16.row.col.f32.bf16.bf16.f32 "
        "{%0,%1,%2,%3}, {%4,%5,%6,%7}, {%8,%9}, {%0,%1,%2,%3};"
        : "+f"(d[0]), "+f"(d[1]), "+f"(d[2]), "+f"(d[3])
        : "r"(a[0]), "r"(a[1]), "r"(a[2]), "r"(a[3]), "r"(b0), "r"(b1));
}

// ldmatrix x4: addr(lane) = base + ((rowbase + (lane&15))*stride + (lane>>4)*4)*4B
__device__ __forceinline__ void ldsm4(unsigned* rg, unsigned addr)
{
    asm volatile("ldmatrix.sync.aligned.m8n8.x4.shared.b16 {%0,%1,%2,%3}, [%4];"
                 : "=r"(rg[0]), "=r"(rg[1]), "=r"(rg[2]), "=r"(rg[3])
                 : "r"(addr));
}

__device__ __forceinline__ unsigned pack_hi(float x, float y,
                                            float& rx, float& ry)
{
    __nv_bfloat162 t = __floats2bfloat162_rn(x, y);
    rx = x - __bfloat162float(t.x);
    ry = y - __bfloat162float(t.y);
    unsigned u; *(__nv_bfloat162*)&u = t; return u;
}
__device__ __forceinline__ unsigned pack_lo(float rx, float ry)
{
    __nv_bfloat162 t = __floats2bfloat162_rn(rx, ry);
    unsigned u; *(__nv_bfloat162*)&u = t; return u;
}

__device__ __forceinline__ void cpa16(unsigned dst, const void* src)
{
    asm volatile("cp.async.cg.shared.global [%0], [%1], 16;"
                 :: "r"(dst), "l"(src));
}
__device__ __forceinline__ void cpa_commit()
{
    asm volatile("cp.async.commit_group;");
}
__device__ __forceinline__ void cpa_wait0()
{
    asm volatile("cp.async.wait_group 0;");
}

// ---------------------------------------------------------------------------
// Prep: fp32 -> bf16 hi/lo word arrays. which: 0=x, 1=qkv_w, 2=out_w
// ---------------------------------------------------------------------------
__global__ void cvt_kernel(const float* __restrict__ src, int which, int n4)
{
    unsigned* dh = (which == 0) ? g_xh : (which == 1) ? g_qwh : g_owh;
    unsigned* dl = (which == 0) ? g_xl : (which == 1) ? g_qwl : g_owl;
    const int i = blockIdx.x * blockDim.x + threadIdx.x;
    if (i < n4) {
        float4 v = ((const float4*)src)[i];
        float rx, ry;
        unsigned h0 = pack_hi(v.x, v.y, rx, ry);
        unsigned l0 = pack_lo(rx, ry);
        unsigned h1 = pack_hi(v.z, v.w, rx, ry);
        unsigned l1 = pack_lo(rx, ry);
        dh[2 * i] = h0; dh[2 * i + 1] = h1;
        dl[2 * i] = l0; dl[2 * i + 1] = l1;
    }
}

// ---------------------------------------------------------------------------
// GEMM: 128x128 tile, cp.async double-buffered, ldmatrix fragment loads.
// MODE 0: A=x, W=qkv_w -> scatter g_qh/g_ql (pad zeroed)
// MODE 1: A=ctx, W=out_w -> fp32 out
// ---------------------------------------------------------------------------
#define KW 20

template <int MODE>
__global__ __launch_bounds__(256, 2) void gemm_bf16_kernel(
    const float* __restrict__ bias, const unsigned int* __restrict__ kpm,
    float* __restrict__ out)
{
    extern __shared__ unsigned dynsm[];   // [2 stages][Ah Al Wh Wl][2560]
    const unsigned *Ah, *Al, *Wh, *Wl;
    if (MODE == 0) { Ah = g_xh;  Al = g_xl;  Wh = g_qwh; Wl = g_qwl; }
    else           { Ah = g_cth; Al = g_ctl; Wh = g_owh; Wl = g_owl; }

    const int tid = threadIdx.x, lane = tid & 31, warp = tid >> 5;
    const int wm = warp >> 1, wn = warp & 1;
    const int m0 = blockIdx.y * 128, n0 = blockIdx.x * 128;
    const int r = lane >> 2, cc = lane & 3;
    const int lrow16 = lane & 15;
    const int lkoff4 = (lane >> 4) * 4;

    const unsigned sbase = (unsigned)__cvta_generic_to_shared(dynsm);

    const int c0 = tid, c1 = tid + 256;
    const int row0 = c0 >> 2, off0 = (c0 & 3) * 4;
    const int row1 = c1 >> 2, off1 = (c1 & 3) * 4;
    const unsigned so0 = (unsigned)(row0 * KW + off0) * 4u;
    const unsigned so1 = (unsigned)(row1 * KW + off1) * 4u;
    const size_t ga0 = (size_t)(m0 + row0) * 512 + off0;
    const size_t ga1 = (size_t)(m0 + row1) * 512 + off1;
    const size_t gb0 = (size_t)(n0 + row0) * 512 + off0;
    const size_t gb1 = (size_t)(n0 + row1) * 512 + off1;

    float acc[2][8][4];
#pragma unroll
    for (int i = 0; i < 2; i++)
#pragma unroll
        for (int j = 0; j < 8; j++)
#pragma unroll
            for (int c = 0; c < 4; c++) acc[i][j][c] = 0.0f;

#define ISSUE(kt, st) do {                                                  \
    const int kk_ = (kt) * 16;                                              \
    const unsigned sb_ = sbase + (unsigned)(st) * 40960u;                   \
    cpa16(sb_ +      0u + so0, Ah + ga0 + kk_);                             \
    cpa16(sb_ +      0u + so1, Ah + ga1 + kk_);                             \
    cpa16(sb_ + 10240u + so0, Al + ga0 + kk_);                              \
    cpa16(sb_ + 10240u + so1, Al + ga1 + kk_);                              \
    cpa16(sb_ + 20480u + so0, Wh + gb0 + kk_);                              \
    cpa16(sb_ + 20480u + so1, Wh + gb1 + kk_);                              \
    cpa16(sb_ + 30720u + so0, Wl + gb0 + kk_);                              \
    cpa16(sb_ + 30720u + so1, Wl + gb1 + kk_);                              \
    cpa_commit(); } while (0)

    ISSUE(0, 0);

    for (int kt = 0; kt < 32; kt++) {
        cpa_wait0();
        __syncthreads();
        if (kt < 31) ISSUE(kt + 1, (kt + 1) & 1);

        const unsigned stoff = sbase + (unsigned)(kt & 1) * 40960u;

#pragma unroll
        for (int half = 0; half < 2; half++) {
            const int kwb = half * 8;
            unsigned ah[2][4], al[2][4];
#pragma unroll
            for (int mi = 0; mi < 2; mi++) {
                const unsigned aoff = (unsigned)
                    ((wm * 32 + mi * 16 + lrow16) * KW + kwb + lkoff4) * 4u;
                ldsm4(ah[mi], stoff + aoff);
                ldsm4(al[mi], stoff + 10240u + aoff);
            }
#pragma unroll
            for (int p = 0; p < 4; p++) {
                const unsigned boff = (unsigned)
                    ((wn * 64 + p * 16 + lrow16) * KW + kwb + lkoff4) * 4u;
                unsigned bh[4], bl[4];
                ldsm4(bh, stoff + 20480u + boff);
                ldsm4(bl, stoff + 30720u + boff);
#pragma unroll
                for (int mi = 0; mi < 2; mi++) {
                    mma_bf16(acc[mi][2 * p],     ah[mi], bh[0], bh[2]);
                    mma_bf16(acc[mi][2 * p],     ah[mi], bl[0], bl[2]);
                    mma_bf16(acc[mi][2 * p],     al[mi], bh[0], bh[2]);
                    mma_bf16(acc[mi][2 * p + 1], ah[mi], bh[1], bh[3]);
                    mma_bf16(acc[mi][2 * p + 1], ah[mi], bl[1], bl[3]);
                    mma_bf16(acc[mi][2 * p + 1], al[mi], bh[1], bh[3]);
                }
            }
        }
        __syncthreads();
    }
#undef ISSUE

#pragma unroll
    for (int mi = 0; mi < 2; mi++) {
        const int mbase = m0 + wm * 32 + mi * 16 + r;
#pragma unroll
        for (int rr = 0; rr < 2; rr++) {
            const int m = mbase + rr * 8;
            if (MODE == 0) {
                const int b = m >> 10, s = m & 1023;
                const bool pad = (kpm[b * 1024 + s] != 0u);
#pragma unroll
                for (int ni = 0; ni < 8; ni++) {
                    const int c = n0 + wn * 64 + ni * 8 + cc * 2;
                    const float v0 = pad ? 0.0f : (acc[mi][ni][rr * 2]     + bias[c]);
                    const float v1 = pad ? 0.0f : (acc[mi][ni][rr * 2 + 1] + bias[c + 1]);
                    const int which = c >> 10;
                    const int e = c & 1023;
                    const int hh = e >> 6, d = e & 63;
                    const size_t idx = (size_t)which * PER
                                     + ((size_t)(b * HH + hh) * SS + s) * DKK + d;
                    __nv_bfloat162 hv, lv;
                    hv.x = __float2bfloat16(v0);
                    lv.x = __float2bfloat16(v0 - __bfloat162float(hv.x));
                    hv.y = __float2bfloat16(v1);
                    lv.y = __float2bfloat16(v1 - __bfloat162float(hv.y));
                    *(__nv_bfloat162*)&g_qh[idx] = hv;
                    *(__nv_bfloat162*)&g_ql[idx] = lv;
                }
            } else {
#pragma unroll
                for (int ni = 0; ni < 8; ni++) {
                    const int n = n0 + wn * 64 + ni * 8 + cc * 2;
                    out[(size_t)m * 1024 + n]     = acc[mi][ni][rr * 2]     + bias[n];
                    out[(size_t)m * 1024 + n + 1] = acc[mi][ni][rr * 2 + 1] + bias[n + 1];
                }
            }
        }
    }
}

// ---------------------------------------------------------------------------
// Attention Pass A: raw scores -> wout (valid tiles only), stats -> g_m/g_linv
// CTA = (b, h, 128 q rows); tiles nt > blockIdx.x skipped (fully masked).
// ---------------------------------------------------------------------------
#define QS 36

__global__ __launch_bounds__(256) void attn_score_kernel(
    const unsigned int* __restrict__ kpm, float* __restrict__ wout)
{
    extern __shared__ unsigned sm[];
    unsigned* sQh = sm;                     // 128*36
    unsigned* sQl = sQh + 128 * QS;
    unsigned* sKh = sQl + 128 * QS;
    unsigned* sKl = sKh + 128 * QS;
    unsigned* sKp = sKl + 128 * QS;

    const int b = blockIdx.z, h = blockIdx.y, q0 = blockIdx.x * 128;
    const int tid = threadIdx.x, lane = tid & 31, w = tid >> 5;
    const int r = lane >> 2, cc = lane & 3;
    const int lrow16 = lane & 15;
    const int lkoff4 = (lane >> 4) * 4;

    const unsigned sKh_u = (unsigned)__cvta_generic_to_shared(sKh);
    const unsigned KLOFF = 128u * QS * 4u;  // sKl - sKh in bytes

    const unsigned* qhw = (const unsigned*)g_qh;
    const unsigned* qlw = (const unsigned*)g_ql;
    const size_t qbase = ((size_t)(b * HH + h) * SS + q0) * 32;
    const size_t kbase = (size_t)PER / 2 + ((size_t)(b * HH + h) * SS) * 32;

    for (int i = tid; i < 1024; i += 256) {
        const int row = i >> 3, off = (i & 7) * 4;
        *(uint4*)&sQh[row * QS + off] = *(const uint4*)(qhw + qbase + row * 32 + off);
        *(uint4*)&sQl[row * QS + off] = *(const uint4*)(qlw + qbase + row * 32 + off);
    }
    __syncthreads();

    const int qr = w * 16 + r;
    unsigned aQh[4][4], aQl[4][4];
#pragma unroll
    for (int ks = 0; ks < 4; ks++) {
        const int bw = ks * 8 + cc;
        aQh[ks][0] = sQh[qr * QS + bw];
        aQh[ks][1] = sQh[(qr + 8) * QS + bw];
        aQh[ks][2] = sQh[qr * QS + bw + 4];
        aQh[ks][3] = sQh[(qr + 8) * QS + bw + 4];
        aQl[ks][0] = sQl[qr * QS + bw];
        aQl[ks][1] = sQl[(qr + 8) * QS + bw];
        aQl[ks][2] = sQl[qr * QS + bw + 4];
        aQl[ks][3] = sQl[(qr + 8) * QS + bw + 4];
    }

    const int row0 = q0 + qr, row1 = row0 + 8;
    float* wrow0 = wout + ((size_t)(b * HH + h) * SS + row0) * SS;
    float* wrow1 = wout + ((size_t)(b * HH + h) * SS + row1) * SS;

    float m_run[2] = {-1e30f, -1e30f};
    float l_run[2] = {0.0f, 0.0f};

    const int ntmax = blockIdx.x;
    for (int nt = 0; nt <= ntmax; nt++) {
        __syncthreads();
        for (int i = tid; i < 1024; i += 256) {
            const int row = i >> 3, off = (i & 7) * 4;
            const size_t g = kbase + (size_t)(nt * 128 + row) * 32 + off;
            *(uint4*)&sKh[row * QS + off] = *(const uint4*)(qhw + g);
            *(uint4*)&sKl[row * QS + off] = *(const uint4*)(qlw + g);
        }
        if (tid < 128) sKp[tid] = kpm[b * 1024 + nt * 128 + tid];
        __syncthreads();

        float acc[16][4];
#pragma unroll
        for (int ni = 0; ni < 16; ni++)
#pragma unroll
            for (int c = 0; c < 4; c++) acc[ni][c] = 0.0f;

#pragma unroll
        for (int ks = 0; ks < 4; ks++) {
#pragma unroll
            for (int p = 0; p < 8; p++) {
                const unsigned koff = (unsigned)
                    ((p * 16 + lrow16) * QS + ks * 8 + lkoff4) * 4u;
                unsigned bh[4], bl[4];
                ldsm4(bh, sKh_u + koff);
                ldsm4(bl, sKh_u + KLOFF + koff);
                mma_bf16(acc[2 * p],     aQh[ks], bh[0], bh[2]);
                mma_bf16(acc[2 * p],     aQh[ks], bl[0], bl[2]);
                mma_bf16(acc[2 * p],     aQl[ks], bh[0], bh[2]);
                mma_bf16(acc[2 * p + 1], aQh[ks], bh[1], bh[3]);
                mma_bf16(acc[2 * p + 1], aQh[ks], bl[1], bl[3]);
                mma_bf16(acc[2 * p + 1], aQl[ks], bh[1], bh[3]);
            }
        }

#pragma unroll
        for (int ni = 0; ni < 16; ni++) {
            const int colb = ni * 8 + cc * 2;
            const int col = nt * 128 + colb;
#pragma unroll
            for (int e = 0; e < 2; e++) {
                const bool pad = (sKp[colb + e] != 0u);
                float s0 = acc[ni][e] * 0.125f;
                if (col + e > row0) s0 += NEGV;
                if (pad) s0 = NEGV;
                acc[ni][e] = s0;
                float s1 = acc[ni][2 + e] * 0.125f;
                if (col + e > row1) s1 += NEGV;
                if (pad) s1 = NEGV;
                acc[ni][2 + e] = s1;
            }
            *(float2*)(wrow0 + col) = make_float2(acc[ni][0], acc[ni][1]);
            *(float2*)(wrow1 + col) = make_float2(acc[ni][2], acc[ni][3]);
        }

        float tm0 = -1e30f, tm1 = -1e30f;
#pragma unroll
        for (int ni = 0; ni < 16; ni++) {
            tm0 = fmaxf(tm0, fmaxf(acc[ni][0], acc[ni][1]));
            tm1 = fmaxf(tm1, fmaxf(acc[ni][2], acc[ni][3]));
        }
        tm0 = fmaxf(tm0, __shfl_xor_sync(0xFFFFFFFFu, tm0, 1));
        tm0 = fmaxf(tm0, __shfl_xor_sync(0xFFFFFFFFu, tm0, 2));
        tm1 = fmaxf(tm1, __shfl_xor_sync(0xFFFFFFFFu, tm1, 1));
        tm1 = fmaxf(tm1, __shfl_xor_sync(0xFFFFFFFFu, tm1, 2));
        const float nm0 = fmaxf(m_run[0], tm0);
        const float nm1 = fmaxf(m_run[1], tm1);
        float s0 = 0.0f, s1 = 0.0f;
#pragma unroll
        for (int ni = 0; ni < 16; ni++) {
            s0 += __expf(acc[ni][0] - nm0) + __expf(acc[ni][1] - nm0);
            s1 += __expf(acc[ni][2] - nm1) + __expf(acc[ni][3] - nm1);
        }
        s0 += __shfl_xor_sync(0xFFFFFFFFu, s0, 1);
        s0 += __shfl_xor_sync(0xFFFFFFFFu, s0, 2);
        s1 += __shfl_xor_sync(0xFFFFFFFFu, s1, 1);
        s1 += __shfl_xor_sync(0xFFFFFFFFu, s1, 2);
        l_run[0] = l_run[0] * __expf(m_run[0] - nm0) + s0;
        l_run[1] = l_run[1] * __expf(m_run[1] - nm1) + s1;
        m_run[0] = nm0; m_run[1] = nm1;
    }

    if (cc == 0) {
        const int sb_ = (b * HH + h) * SS;
        g_m[sb_ + row0] = m_run[0];
        g_m[sb_ + row1] = m_run[1];
        g_linv[sb_ + row0] = 1.0f / l_run[0];
        g_linv[sb_ + row1] = 1.0f / l_run[1];
    }
}

// ---------------------------------------------------------------------------
// Attention Pass B: w = exp(s-m)/l (write back), ctx = W @ V (hi/lo bf16 out).
// Fully-masked tiles: zero weights, skip compute.
// ---------------------------------------------------------------------------
#define WS 68

__global__ __launch_bounds__(256) void attn_av_kernel(float* __restrict__ wout)
{
    extern __shared__ unsigned sm[];
    unsigned* sWh = sm;                     // 128*68
    unsigned* sWl = sWh + 128 * WS;
    unsigned* sVh = sWl + 128 * WS;         // 64*68
    unsigned* sVl = sVh + 64 * WS;
    float*    sM  = (float*)(sVl + 64 * WS);
    float*    sLi = sM + 128;

    const int b = blockIdx.z, h = blockIdx.y, q0 = blockIdx.x * 128;
    const int tid = threadIdx.x, lane = tid & 31, w = tid >> 5;
    const int r = lane >> 2, cc = lane & 3;
    const int lrow16 = lane & 15;
    const int lkoff4 = (lane >> 4) * 4;

    const unsigned sWh_u = (unsigned)__cvta_generic_to_shared(sWh);
    const unsigned sVh_u = (unsigned)__cvta_generic_to_shared(sVh);
    const unsigned WLOFF = 128u * WS * 4u;
    const unsigned VLOFF = 64u * WS * 4u;

    const unsigned* vhw = (const unsigned*)g_qh + (size_t)PER
                        + ((size_t)(b * HH + h) * SS) * 32;
    const unsigned* vlw = (const unsigned*)g_ql + (size_t)PER
                        + ((size_t)(b * HH + h) * SS) * 32;
    float* wbase = wout + ((size_t)(b * HH + h) * SS + q0) * SS;

    if (tid < 128) {
        const int sb_ = (b * HH + h) * SS + q0;
        sM[tid]  = g_m[sb_ + tid];
        sLi[tid] = g_linv[sb_ + tid];
    }
    __syncthreads();

    float acc[8][4];
#pragma unroll
    for (int ni = 0; ni < 8; ni++)
#pragma unroll
        for (int c = 0; c < 4; c++) acc[ni][c] = 0.0f;

    const int ktmax = blockIdx.x;

    for (int kt = 0; kt <= ktmax; kt++) {
        if (kt > 0) __syncthreads();
        for (int i = tid; i < 4096; i += 256) {
            const int row = i >> 5, c4 = (i & 31) * 4;
            float* p = wbase + (size_t)row * SS + kt * 128 + c4;
            float4 s = *(const float4*)p;
            const float mm = sM[row], li = sLi[row];
            float4 wv;
            wv.x = __expf(s.x - mm) * li;
            wv.y = __expf(s.y - mm) * li;
            wv.z = __expf(s.z - mm) * li;
            wv.w = __expf(s.w - mm) * li;
            *(float4*)p = wv;
            float rx, ry;
            unsigned h0 = pack_hi(wv.x, wv.y, rx, ry); unsigned l0 = pack_lo(rx, ry);
            unsigned h1 = pack_hi(wv.z, wv.w, rx, ry); unsigned l1 = pack_lo(rx, ry);
            const int base = row * WS + (c4 >> 1);
            sWh[base] = h0; sWh[base + 1] = h1;
            sWl[base] = l0; sWl[base + 1] = l1;
        }
        {
            __nv_bfloat16* tVh = (__nv_bfloat16*)sVh;
            __nv_bfloat16* tVl = (__nv_bfloat16*)sVl;
            for (int i = tid; i < 4096; i += 256) {
                const int key = i >> 5, dw = i & 31;
                const size_t g = (size_t)(kt * 128 + key) * 32 + dw;
                unsigned wh = vhw[g];
                unsigned wl = vlw[g];
                __nv_bfloat162 h2 = *(__nv_bfloat162*)&wh;
                __nv_bfloat162 l2 = *(__nv_bfloat162*)&wl;
                tVh[(2 * dw) * (2 * WS) + key]     = h2.x;
                tVh[(2 * dw + 1) * (2 * WS) + key] = h2.y;
                tVl[(2 * dw) * (2 * WS) + key]     = l2.x;
                tVl[(2 * dw + 1) * (2 * WS) + key] = l2.y;
            }
        }
        __syncthreads();

#pragma unroll
        for (int ks = 0; ks < 8; ks++) {
            const unsigned woff = (unsigned)
                ((w * 16 + lrow16) * WS + ks * 8 + lkoff4) * 4u;
            unsigned ah[4], al[4];
            ldsm4(ah, sWh_u + woff);
            ldsm4(al, sWh_u + WLOFF + woff);
#pragma unroll
            for (int p = 0; p < 4; p++) {
                const unsigned voff = (unsigned)
                    ((p * 16 + lrow16) * WS + ks * 8 + lkoff4) * 4u;
                unsigned bh[4], bl[4];
                ldsm4(bh, sVh_u + voff);
                ldsm4(bl, sVh_u + VLOFF + voff);
                mma_bf16(acc[2 * p],     ah, bh[0], bh[2]);
                mma_bf16(acc[2 * p],     ah, bl[0], bl[2]);
                mma_bf16(acc[2 * p],     al, bh[0], bh[2]);
                mma_bf16(acc[2 * p + 1], ah, bh[1], bh[3]);
                mma_bf16(acc[2 * p + 1], ah, bl[1], bl[3]);
                mma_bf16(acc[2 * p + 1], al, bh[1], bh[3]);
            }
        }
    }

    // zero-fill weights for fully-masked tiles
    {
        const float4 z4 = make_float4(0.f, 0.f, 0.f, 0.f);
        for (int kt = ktmax + 1; kt < 8; kt++)
            for (int i = tid; i < 4096; i += 256) {
                const int row = i >> 5, c4 = (i & 31) * 4;
                *(float4*)(wbase + (size_t)row * SS + kt * 128 + c4) = z4;
            }
    }

    // ctx epilogue: hi/lo bf16
    __nv_bfloat16* cth = (__nv_bfloat16*)g_cth;
    __nv_bfloat16* ctl = (__nv_bfloat16*)g_ctl;
    const int qr = w * 16 + r;
    const size_t o0 = ((size_t)(b * SS + q0 + qr)) * EE + h * DKK;
    const size_t o1 = ((size_t)(b * SS + q0 + qr + 8)) * EE + h * DKK;
#pragma unroll
    for (int ni = 0; ni < 8; ni++) {
        const int d0 = ni * 8 + cc * 2;
        __nv_bfloat162 hv, lv;
        hv.x = __float2bfloat16(acc[ni][0]);
        lv.x = __float2bfloat16(acc[ni][0] - __bfloat162float(hv.x));
        hv.y = __float2bfloat16(acc[ni][1]);
        lv.y = __float2bfloat16(acc[ni][1] - __bfloat162float(hv.y));
        *(__nv_bfloat162*)(cth + o0 + d0) = hv;
        *(__nv_bfloat162*)(ctl + o0 + d0) = lv;
        hv.x = __float2bfloat16(acc[ni][2]);
        lv.x = __float2bfloat16(acc[ni][2] - __bfloat162float(hv.x));
        hv.y = __float2bfloat16(acc[ni][3]);
        lv.y = __float2bfloat16(acc[ni][3] - __bfloat162float(hv.y));
        *(__nv_bfloat162*)(cth + o1 + d0) = hv;
        *(__nv_bfloat162*)(ctl + o1 + d0) = lv;
    }
}

// ---------------------------------------------------------------------------
extern "C" void kernel_launch(void* const* d_in, const int* in_sizes, int n_in,
                              void* d_out, int out_size)
{
    const float*        x     = (const float*)d_in[0];
    const unsigned int* kpm   = (const unsigned int*)d_in[2];
    const float*        qkv_w = (const float*)d_in[3];
    const float*        qkv_b = (const float*)d_in[4];
    const float*        out_w = (const float*)d_in[5];
    const float*        out_b = (const float*)d_in[6];

    float* out  = (float*)d_out;
    float* wout = out + (size_t)BB * SS * EE;

    const int gemmSmem  = 2 * 4 * 2560 * 4;                         // 80 KB
    const int scoreSmem = (4 * 128 * QS + 128) * 4;                 // ~74 KB
    const int avSmem    = (2 * 128 * WS + 2 * 64 * WS + 256) * 4;   // ~105 KB
    cudaFuncSetAttribute(gemm_bf16_kernel<0>,
                         cudaFuncAttributeMaxDynamicSharedMemorySize, gemmSmem);
    cudaFuncSetAttribute(gemm_bf16_kernel<1>,
                         cudaFuncAttributeMaxDynamicSharedMemorySize, gemmSmem);
    cudaFuncSetAttribute(attn_score_kernel,
                         cudaFuncAttributeMaxDynamicSharedMemorySize, scoreSmem);
    cudaFuncSetAttribute(attn_av_kernel,
                         cudaFuncAttributeMaxDynamicSharedMemorySize, avSmem);

    // 0) one-time conversions
    cvt_kernel<<<4096, 256>>>(x,     0, 4096 * 256);
    cvt_kernel<<<3072, 256>>>(qkv_w, 1, 3072 * 256);
    cvt_kernel<<<1024, 256>>>(out_w, 2, 1024 * 256);

    // 1) QKV projection -> g_qh/g_ql
    gemm_bf16_kernel<0><<<dim3(24, 32), 256, gemmSmem>>>(qkv_b, kpm, nullptr);

    // 2a) scores + stats
    attn_score_kernel<<<dim3(8, HH, BB), 256, scoreSmem>>>(kpm, wout);

    // 2b) softmax weights + ctx
    attn_av_kernel<<<dim3(8, HH, BB), 256, avSmem>>>(wout);

    // 3) output projection
    gemm_bf16_kernel<1><<<dim3(8, 32), 256, gemmSmem>>>(out_b, nullptr, out);
}